// round 1
// baseline (speedup 1.0000x reference)
#include <cuda_runtime.h>

// OpeningLoss2D: mean((x - grey_opening_2x2(x))^2) over [8,16,512,512] fp32.
//
// Separable formulation per channel slice:
//   hm(i,j) = min(x(i, max(j-1,0)), x(i,j))            (horizontal erosion)
//   er(i,j) = min(hm(max(i-1,0), j), hm(i,j))          (vertical erosion)
//   hM(i,j) = max(er(i,j), er(i, min(j+1,W-1)))        (horizontal dilation, er-index clamp)
//   sm(i,j) = max(hM(i,j), hM(min(i+1,H-1), j))        (vertical dilation, er-index clamp)
//
// Each warp processes a 256-col x 32-row strip; each thread owns 8 columns
// (two float4 loads per row) and pipelines rows in registers. Horizontal halo
// via warp shuffles; strip-edge columns via predicated scalar loads.

#define FULLMASK 0xffffffffu

static const int Hc = 512;
static const int Wc = 512;
static const int THR = 32;          // rows per strip
static const int NBLK = 512;        // 512 blocks * 8 warps = 4096 strips

__device__ float g_partials[NBLK];

__global__ void __launch_bounds__(256, 3)
opening_kernel(const float* __restrict__ X) {
    const int warpId = threadIdx.x >> 5;
    const int lane   = threadIdx.x & 31;
    const int gw     = blockIdx.x * 8 + warpId;   // 0..4095
    const int slice  = gw >> 5;                   // 0..127 (B*C)
    const int rem    = gw & 31;
    const int r0     = (rem >> 1) << 5;           // row strip * 32
    const int cs     = (rem & 1) << 8;            // col strip * 256
    const float* S   = X + (size_t)slice * (Hc * Wc);
    const int c0     = cs + (lane << 3);          // this thread's first column
    const bool rightedge = (c0 + 8 >= Wc);        // col 511 owned by this thread
    const int ecol   = (lane == 0) ? max(cs - 1, 0) : min(cs + 256, Wc - 1);
    const bool eload = (lane == 0) || (lane == 31);

    float v[8], vprev[8];
    float hm[9], hm_prev[9];
    float hM_prev[8];
    float acc = 0.f;

    // Load physical row p=0 : global row clamp(r0-1)
    {
        int gr0 = max(r0 - 1, 0);
        const float4* p0 = reinterpret_cast<const float4*>(S + gr0 * Wc + c0);
        float4 a = __ldg(p0), b = __ldg(p0 + 1);
        v[0]=a.x; v[1]=a.y; v[2]=a.z; v[3]=a.w;
        v[4]=b.x; v[5]=b.y; v[6]=b.z; v[7]=b.w;
    }
    float eg = 0.f;
    if (eload) eg = __ldg(S + max(r0 - 1, 0) * Wc + ecol);

    // Row pipeline: iteration p holds x row (r0-1+p), clamped.
    // er row e = r0+p-1 computed at p>=1; smooth row e-1 emitted at p>=2.
    #pragma unroll 2
    for (int p = 0; p <= THR + 1; ++p) {
        // Prefetch next row (r0 + p, clamped at bottom)
        float vn[8]; float egn = 0.f;
        if (p <= THR) {
            int grn = min(r0 + p, Hc - 1);
            const float4* pn = reinterpret_cast<const float4*>(S + grn * Wc + c0);
            float4 an = __ldg(pn), bn = __ldg(pn + 1);
            vn[0]=an.x; vn[1]=an.y; vn[2]=an.z; vn[3]=an.w;
            vn[4]=bn.x; vn[5]=bn.y; vn[6]=bn.z; vn[7]=bn.w;
            if (eload) egn = __ldg(S + grn * Wc + ecol);
        }

        // Horizontal erosion of current row (cols c0-1 .. c0+8 -> hm[0..8])
        float left  = __shfl_up_sync(FULLMASK, v[7], 1);
        float right = __shfl_down_sync(FULLMASK, v[0], 1);
        if (lane == 0)  left  = eg;   // global col cs-1 (clamped)
        if (lane == 31) right = eg;   // global col cs+256 (clamped)
        hm[0] = fminf(left, v[0]);
        #pragma unroll
        for (int k = 1; k < 8; ++k) hm[k] = fminf(v[k-1], v[k]);
        hm[8] = fminf(v[7], right);

        if (p >= 1) {
            // Vertical erosion: er row e = r0+p-1
            float er[9];
            #pragma unroll
            for (int k = 0; k < 9; ++k) er[k] = fminf(hm_prev[k], hm[k]);
            // Horizontal dilation with er-column clamp at W-1
            float hM[8];
            #pragma unroll
            for (int k = 0; k < 8; ++k) hM[k] = fmaxf(er[k], er[k+1]);
            if (rightedge) hM[7] = er[7];
            // er-row clamp at H-1: row H doesn't exist -> replicate previous hM
            if (r0 + p - 1 >= Hc) {
                #pragma unroll
                for (int k = 0; k < 8; ++k) hM[k] = hM_prev[k];
            }
            if (p >= 2) {
                // smooth row (r0+p-2); its x values are vprev (loaded at iter p-1)
                #pragma unroll
                for (int k = 0; k < 8; ++k) {
                    float s = fmaxf(hM_prev[k], hM[k]);
                    float d = vprev[k] - s;
                    acc = fmaf(d, d, acc);
                }
            }
            #pragma unroll
            for (int k = 0; k < 8; ++k) hM_prev[k] = hM[k];
        }

        #pragma unroll
        for (int k = 0; k < 9; ++k) hm_prev[k] = hm[k];
        #pragma unroll
        for (int k = 0; k < 8; ++k) { vprev[k] = v[k]; v[k] = vn[k]; }
        eg = egn;
    }

    // Warp reduce
    #pragma unroll
    for (int off = 16; off; off >>= 1)
        acc += __shfl_down_sync(FULLMASK, acc, off);

    __shared__ float wsum[8];
    if (lane == 0) wsum[warpId] = acc;
    __syncthreads();
    if (threadIdx.x == 0) {
        float s = 0.f;
        #pragma unroll
        for (int i = 0; i < 8; ++i) s += wsum[i];
        g_partials[blockIdx.x] = s;
    }
}

__global__ void finalize_kernel(float* __restrict__ out) {
    __shared__ float sh[256];
    float s = 0.f;
    for (int i = threadIdx.x; i < NBLK; i += 256) s += g_partials[i];
    sh[threadIdx.x] = s;
    __syncthreads();
    #pragma unroll
    for (int off = 128; off; off >>= 1) {
        if (threadIdx.x < off) sh[threadIdx.x] += sh[threadIdx.x + off];
        __syncthreads();
    }
    if (threadIdx.x == 0)
        out[0] = sh[0] * (1.0f / 33554432.0f);   // mean over 8*16*512*512
}

extern "C" void kernel_launch(void* const* d_in, const int* in_sizes, int n_in,
                              void* d_out, int out_size) {
    const float* X = (const float*)d_in[0];
    opening_kernel<<<NBLK, 256>>>(X);
    finalize_kernel<<<1, 256>>>((float*)d_out);
}

// round 2
// speedup vs baseline: 1.0305x; 1.0305x over previous
#include <cuda_runtime.h>

// OpeningLoss2D: mean((x - grey_opening_2x2(x))^2) over [8,16,512,512] fp32.
// Separable per-slice: hmin2 -> vmin2 -> hmax2 -> vmax2 (scipy w=2 semantics,
// symmetric/edge-replicate boundaries, er-index clamping on the dilation).
//
// Warp strip = 128 cols x 32 rows; thread owns 4 cols (one LDG.128 per row).
// Register row pipeline with prefetch depth 2. Horizontal halo via shuffles +
// predicated scalar edge loads. Single kernel: block partials + last-block
// reduction (threadfence + atomic counter, counter reset => deterministic).

#define FULLMASK 0xffffffffu

static const int Hc = 512;
static const int Wc = 512;
static const int THR = 32;           // rows per strip
static const int NBLK = 1024;        // 1024 blocks * 8 warps = 8192 strips

__device__ float g_partials[NBLK];
__device__ unsigned int g_count = 0;

__global__ void __launch_bounds__(256, 4)
opening_kernel(const float* __restrict__ X, float* __restrict__ out) {
    const int warpId = threadIdx.x >> 5;
    const int lane   = threadIdx.x & 31;
    const int gw     = blockIdx.x * 8 + warpId;   // 0..8191
    const int slice  = gw >> 6;                   // 0..127 (B*C)
    const int rem    = gw & 63;                   // 16 row-strips x 4 col-strips
    const int r0     = (rem >> 2) << 5;           // row strip * 32
    const int cs     = (rem & 3) << 7;            // col strip * 128
    const float* S   = X + (size_t)slice * (Hc * Wc);
    const int c0     = cs + (lane << 2);          // thread's first column
    const bool rightedge = (c0 + 4 >= Wc);        // owns col 511
    const int ecol   = (lane == 0) ? max(cs - 1, 0) : min(cs + 128, Wc - 1);
    const bool eload = (lane == 0) || (lane == 31);

    float a0[4], a1[4], a2[4], vprev[4];
    float hm[5], hm_prev[5], hM_prev[4];
    float eg0, eg1, eg2;
    float acc = 0.f;

    // gr(p) = clamp(r0-1+p, 0, Hc-1); preload p=0 and p=1
    {
        int g0 = max(r0 - 1, 0);
        float4 t = __ldg(reinterpret_cast<const float4*>(S + g0 * Wc + c0));
        float4 u = __ldg(reinterpret_cast<const float4*>(S + r0 * Wc + c0));
        a0[0]=t.x; a0[1]=t.y; a0[2]=t.z; a0[3]=t.w;
        a1[0]=u.x; a1[1]=u.y; a1[2]=u.z; a1[3]=u.w;
        eg0 = eload ? __ldg(S + g0 * Wc + ecol) : 0.f;
        eg1 = eload ? __ldg(S + r0 * Wc + ecol) : 0.f;
    }

    // Iteration p uses x row gr(p); er row e=r0+p-1 at p>=1; smooth row e-1 at p>=2.
    #pragma unroll 2
    for (int p = 0; p <= THR + 1; ++p) {
        // Prefetch row gr(p+2)
        if (p + 2 <= THR + 1) {
            int grn = min(r0 + p + 1, Hc - 1);
            float4 t = __ldg(reinterpret_cast<const float4*>(S + grn * Wc + c0));
            a2[0]=t.x; a2[1]=t.y; a2[2]=t.z; a2[3]=t.w;
            eg2 = eload ? __ldg(S + grn * Wc + ecol) : 0.f;
        }

        // Horizontal erosion of row gr(p): hm[k] = min over {c0+k-1, c0+k}, k=0..4
        float left  = __shfl_up_sync(FULLMASK, a0[3], 1);
        float right = __shfl_down_sync(FULLMASK, a0[0], 1);
        if (lane == 0)  left  = eg0;   // col cs-1 (clamped)
        if (lane == 31) right = eg0;   // col cs+128 (clamped)
        hm[0] = fminf(left, a0[0]);
        hm[1] = fminf(a0[0], a0[1]);
        hm[2] = fminf(a0[1], a0[2]);
        hm[3] = fminf(a0[2], a0[3]);
        hm[4] = fminf(a0[3], right);

        if (p >= 1) {
            float er[5];
            #pragma unroll
            for (int k = 0; k < 5; ++k) er[k] = fminf(hm_prev[k], hm[k]);
            float hM[4];
            #pragma unroll
            for (int k = 0; k < 4; ++k) hM[k] = fmaxf(er[k], er[k+1]);
            if (rightedge) hM[3] = er[3];          // er-col clamp at W-1
            if (r0 + p - 1 >= Hc) {                // er-row clamp at H-1
                #pragma unroll
                for (int k = 0; k < 4; ++k) hM[k] = hM_prev[k];
            }
            if (p >= 2) {
                #pragma unroll
                for (int k = 0; k < 4; ++k) {
                    float s = fmaxf(hM_prev[k], hM[k]);
                    float d = vprev[k] - s;
                    acc = fmaf(d, d, acc);
                }
            }
            #pragma unroll
            for (int k = 0; k < 4; ++k) hM_prev[k] = hM[k];
        }

        #pragma unroll
        for (int k = 0; k < 5; ++k) hm_prev[k] = hm[k];
        #pragma unroll
        for (int k = 0; k < 4; ++k) { vprev[k] = a0[k]; a0[k] = a1[k]; a1[k] = a2[k]; }
        eg0 = eg1; eg1 = eg2;
    }

    // Warp reduce
    #pragma unroll
    for (int off = 16; off; off >>= 1)
        acc += __shfl_down_sync(FULLMASK, acc, off);

    __shared__ float wsum[8];
    __shared__ bool amLast;
    __shared__ float sh[256];
    if (lane == 0) wsum[warpId] = acc;
    __syncthreads();
    if (threadIdx.x == 0) {
        float s = 0.f;
        #pragma unroll
        for (int i = 0; i < 8; ++i) s += wsum[i];
        g_partials[blockIdx.x] = s;
        __threadfence();
        unsigned int old = atomicAdd(&g_count, 1u);
        amLast = (old == (unsigned)(NBLK - 1));
    }
    __syncthreads();

    if (amLast) {
        float s = 0.f;
        for (int i = threadIdx.x; i < NBLK; i += 256) s += g_partials[i];
        sh[threadIdx.x] = s;
        __syncthreads();
        #pragma unroll
        for (int off = 128; off; off >>= 1) {
            if (threadIdx.x < off) sh[threadIdx.x] += sh[threadIdx.x + off];
            __syncthreads();
        }
        if (threadIdx.x == 0) {
            out[0] = sh[0] * (1.0f / 33554432.0f);  // mean over 8*16*512*512
            g_count = 0;                            // reset => deterministic replays
        }
    }
}

extern "C" void kernel_launch(void* const* d_in, const int* in_sizes, int n_in,
                              void* d_out, int out_size) {
    const float* X = (const float*)d_in[0];
    opening_kernel<<<NBLK, 256>>>(X, (float*)d_out);
}

// round 3
// speedup vs baseline: 1.3994x; 1.3580x over previous
#include <cuda_runtime.h>
#include <cstdint>

// OpeningLoss2D: mean((x - grey_opening_2x2(x))^2) over [8,16,512,512] fp32.
// Separable: hmin2 -> vmin2 -> hmax2 -> vmax2 (scipy w=2, edge-replicate,
// er-index clamping on dilation).
//
// Block = 128 threads, tile = full 512 cols x 64 rows of one slice.
// Rows stream GMEM->SMEM via cp.async ring (8 slots, 6 in flight) to decouple
// load issue from the compute scoreboard chain. Each thread owns 4 cols;
// vertical recurrence lives in registers; horizontal halo via shuffles plus
// lane-0/31 smem reads. Single kernel, last-block final reduction.

#define FULLMASK 0xffffffffu

static const int Hc = 512;
static const int Wc = 512;
static const int TR = 64;             // rows per tile
static const int NBLK = 1024;         // 128 slices * 8 tiles
static const int RING = 8;
static const int DEPTH = 6;           // cp.async groups in flight

__device__ float g_partials[NBLK];
__device__ unsigned int g_count = 0;

__device__ __forceinline__ void cp_async16(uint32_t saddr, const float* gaddr) {
    asm volatile("cp.async.cg.shared.global [%0], [%1], 16;\n"
                 :: "r"(saddr), "l"(gaddr));
}
__device__ __forceinline__ void cp_commit() {
    asm volatile("cp.async.commit_group;\n" ::: "memory");
}
template <int N>
__device__ __forceinline__ void cp_wait() {
    asm volatile("cp.async.wait_group %0;\n" :: "n"(N) : "memory");
}

__global__ void __launch_bounds__(128, 8)
opening_kernel(const float* __restrict__ X, float* __restrict__ out) {
    __shared__ float ring[RING][Wc];      // 16 KB
    __shared__ float wsum[4];
    __shared__ bool amLast;

    const int t      = threadIdx.x;       // 0..127
    const int lane   = t & 31;
    const int warpId = t >> 5;
    const int tile   = blockIdx.x;        // 0..1023
    const int slice  = tile >> 3;         // 0..127
    const int r0     = (tile & 7) * TR;
    const float* S   = X + (size_t)slice * (Hc * Wc);
    const int c0     = t << 2;            // first owned column
    const bool lastT = (c0 + 4 >= Wc);    // owns col 511

    const uint32_t sbase =
        (uint32_t)__cvta_generic_to_shared(&ring[0][0]) + (uint32_t)(c0 * 4);

    // issue physical row p: global row clamp(r0-1+p, 0, Hc-1)
    #define ISSUE(p) do {                                                   \
        int _gr = min(max(r0 - 1 + (p), 0), Hc - 1);                        \
        cp_async16(sbase + (uint32_t)(((p) & (RING - 1)) * Wc * 4),         \
                   S + (size_t)_gr * Wc + c0);                              \
        cp_commit();                                                        \
    } while (0)

    #pragma unroll
    for (int p = 0; p < DEPTH; ++p) ISSUE(p);

    float vprev[4], hm_prev[5], hM_prev[4];
    float acc = 0.f;

    for (int p = 0; p <= TR + 1; ++p) {
        cp_wait<DEPTH - 1>();             // row p arrived
        __syncthreads();                  // visible to all; prior-step reads done
        if (p + DEPTH <= TR + 1) ISSUE(p + DEPTH);

        const float* row = ring[p & (RING - 1)];
        float4 q = *reinterpret_cast<const float4*>(row + c0);
        float v0 = q.x, v1 = q.y, v2 = q.z, v3 = q.w;

        float L  = __shfl_up_sync(FULLMASK, v3, 1);
        float Rh = __shfl_down_sync(FULLMASK, v0, 1);
        if (lane == 0)  L  = row[max(c0 - 1, 0)];        // cross-warp / left clamp
        if (lane == 31) Rh = row[min(c0 + 4, Wc - 1)];   // cross-warp / right edge

        float hm[5];
        hm[0] = fminf(L,  v0);
        hm[1] = fminf(v0, v1);
        hm[2] = fminf(v1, v2);
        hm[3] = fminf(v2, v3);
        hm[4] = fminf(v3, Rh);

        if (p >= 1) {
            float er[5];
            #pragma unroll
            for (int k = 0; k < 5; ++k) er[k] = fminf(hm_prev[k], hm[k]);
            float hM[4];
            #pragma unroll
            for (int k = 0; k < 4; ++k) hM[k] = fmaxf(er[k], er[k + 1]);
            if (lastT) hM[3] = er[3];                    // er-col clamp at W-1
            if (r0 + p - 1 >= Hc) {                      // er-row clamp at H-1
                #pragma unroll
                for (int k = 0; k < 4; ++k) hM[k] = hM_prev[k];
            }
            if (p >= 2) {
                #pragma unroll
                for (int k = 0; k < 4; ++k) {
                    float s = fmaxf(hM_prev[k], hM[k]);
                    float d = vprev[k] - s;
                    acc = fmaf(d, d, acc);
                }
            }
            #pragma unroll
            for (int k = 0; k < 4; ++k) hM_prev[k] = hM[k];
        }

        #pragma unroll
        for (int k = 0; k < 5; ++k) hm_prev[k] = hm[k];
        vprev[0] = v0; vprev[1] = v1; vprev[2] = v2; vprev[3] = v3;
    }
    #undef ISSUE

    // Warp reduce
    #pragma unroll
    for (int off = 16; off; off >>= 1)
        acc += __shfl_down_sync(FULLMASK, acc, off);
    if (lane == 0) wsum[warpId] = acc;
    __syncthreads();
    if (t == 0) {
        float s = wsum[0] + wsum[1] + wsum[2] + wsum[3];
        g_partials[blockIdx.x] = s;
        __threadfence();
        unsigned int old = atomicAdd(&g_count, 1u);
        amLast = (old == (unsigned)(NBLK - 1));
    }
    __syncthreads();

    if (amLast) {
        __shared__ float sh[128];
        float s = 0.f;
        for (int i = t; i < NBLK; i += 128) s += g_partials[i];
        sh[t] = s;
        __syncthreads();
        #pragma unroll
        for (int off = 64; off; off >>= 1) {
            if (t < off) sh[t] += sh[t + off];
            __syncthreads();
        }
        if (t == 0) {
            out[0] = sh[0] * (1.0f / 33554432.0f);  // mean over 8*16*512*512
            g_count = 0;                            // deterministic graph replays
        }
    }
}

extern "C" void kernel_launch(void* const* d_in, const int* in_sizes, int n_in,
                              void* d_out, int out_size) {
    const float* X = (const float*)d_in[0];
    opening_kernel<<<NBLK, 128>>>(X, (float*)d_out);
}